// round 12
// baseline (speedup 1.0000x reference)
#include <cuda_runtime.h>
#include <cuda_bf16.h>

// ContourIntegrationLayer: depthwise 3x3 conv (center tap zeroed) + residual.
// x: [B=32, H=56, W=56, C=256] fp32 NHWC ; kernel: [3,3,256] fp32.
//
// R12: R11 (cp.async ring, w-pair per thread, zero-slice boundary) but rows
// staged and consumed in PAIRS: one wait_group + one __syncthreads per TWO
// rows (8 syncs/block instead of 16). Ring = 3 pair-stages (60KB dynamic
// smem), copies for pair p+2 issued after barrier p (WAR-safe), lookahead
// up to 2 pairs in flight.

#define BD 32
#define HD 56
#define WD 56
#define C4D 64                 // 256/4 float4 lanes
#define H_SEG 14
#define W_BLK 8                // w per block
#define WSLOT 4
#define NSP 3                  // ring stages (pairs)
#define NSLICE (W_BLK + 2)     // 10 slices per row
#define SLICE_F4 (NSLICE * C4D)    // 640 float4 = 10KB per row
#define ROWSTRIDE (WD * C4D)       // 3584 float4 per image row
#define SMEM_BYTES (NSP * 2 * SLICE_F4 * 16)   // 61440

__device__ __forceinline__ void cp16(float4* dst_smem, const float4* src) {
    unsigned d = (unsigned)__cvta_generic_to_shared(dst_smem);
    asm volatile("cp.async.cg.shared.global [%0], [%1], 16;" :: "r"(d), "l"(src));
}
#define CP_COMMIT() asm volatile("cp.async.commit_group;")
#define CP_WAIT1()  asm volatile("cp.async.wait_group 1;")

__device__ __forceinline__ void fma4(float4& a, const float4& k, const float4& v) {
    a.x = fmaf(k.x, v.x, a.x);
    a.y = fmaf(k.y, v.y, a.y);
    a.z = fmaf(k.z, v.z, a.z);
    a.w = fmaf(k.w, v.w, a.w);
}
__device__ __forceinline__ void add4(float4& a, const float4& v) {
    a.x += v.x; a.y += v.y; a.z += v.z; a.w += v.w;
}

// Copy rows r0, r0+1 of the (b, w0-1..w0+8) strip into a pair-stage.
#define COPY_PAIR(stageptr, r0_)                                        \
{                                                                       \
    const int r0c = (r0_);                                              \
    if (r0c >= 0) {                                                     \
        const int ro = r0c * ROWSTRIDE;                                 \
        if (v1) cp16((stageptr) + tid,        s1 + ro);                 \
        if (v2) cp16((stageptr) + tid + 256,  s2 + ro);                 \
        if (v3) cp16((stageptr) + tid + 512,  s3 + ro);                 \
    }                                                                   \
    if (r0c + 1 < HD) {                                                 \
        const int ro = (r0c + 1) * ROWSTRIDE;                           \
        if (v1) cp16((stageptr) + SLICE_F4 + tid,        s1 + ro);      \
        if (v2) cp16((stageptr) + SLICE_F4 + tid + 256,  s2 + ro);      \
        if (v3) cp16((stageptr) + SLICE_F4 + tid + 512,  s3 + ro);      \
    }                                                                   \
}

// Consume input row r (= h0-1+iidx) from stage half; rotate partials.
#define CONSUME(iidx, half, stagebase)                                           \
{                                                                                \
    const int r = h0 - 1 + (iidx);                                               \
    float4 xs0, xs1, xs2, xs3;                                                   \
    if (r >= 0 && r < HD) {                                                      \
        const float4* sp = (stagebase) + (half) * SLICE_F4 + sbase;              \
        xs0 = sp[0]; xs1 = sp[C4D]; xs2 = sp[2 * C4D]; xs3 = sp[3 * C4D];        \
    } else { xs0 = zf; xs1 = zf; xs2 = zf; xs3 = zf; }                           \
    if ((iidx) >= 2) {                                                           \
        float4 o0 = a00;                                                         \
        fma4(o0, k20, xs0); fma4(o0, k21, xs1); fma4(o0, k22, xs2);              \
        float4 o1 = a01;                                                         \
        fma4(o1, k20, xs1); fma4(o1, k21, xs2); fma4(o1, k22, xs3);              \
        const int ob = out_b0 + (r - 1) * ROWSTRIDE;                             \
        __stcs(op + ob, o0);                                                     \
        __stcs(op + ob + C4D, o1);                                               \
    }                                                                            \
    float4 A0 = a10; add4(A0, xs1); fma4(A0, k10, xs0); fma4(A0, k12, xs2);      \
    float4 B0 = zf;  fma4(B0, k00, xs0); fma4(B0, k01, xs1); fma4(B0, k02, xs2); \
    a00 = A0; a10 = B0;                                                          \
    float4 A1 = a11; add4(A1, xs2); fma4(A1, k10, xs1); fma4(A1, k12, xs3);      \
    float4 B1 = zf;  fma4(B1, k00, xs1); fma4(B1, k01, xs2); fma4(B1, k02, xs3); \
    a01 = A1; a11 = B1;                                                          \
}

__global__ __launch_bounds__(256, 3)
void contour_integration_kernel(const float* __restrict__ x,
                                const float* __restrict__ ker,
                                float* __restrict__ out) {
    extern __shared__ __align__(16) float4 stg[];   // [NSP][2][SLICE_F4]

    const int c4    = threadIdx.x;              // 0..63
    const int wslot = threadIdx.y;              // 0..3
    const int tid   = c4 + wslot * C4D;         // 0..255
    const int w0    = blockIdx.x * W_BLK;
    const int h0    = blockIdx.y * H_SEG;
    const int b     = blockIdx.z;

    const float4 zf = make_float4(0.f, 0.f, 0.f, 0.f);

    // Permanent zero slices for w outside the image (cp never writes them).
    if (w0 == 0 && tid < C4D) {
        #pragma unroll
        for (int s = 0; s < NSP * 2; ++s) stg[s * SLICE_F4 + tid] = zf;
    }
    if (w0 + W_BLK == WD && tid < C4D) {
        #pragma unroll
        for (int s = 0; s < NSP * 2; ++s)
            stg[s * SLICE_F4 + (NSLICE - 1) * C4D + tid] = zf;
    }

    // ---- copy-role: 640 chunks per row; thread does tid, tid+256, (+512 if tid<128)
    const int sl1 = tid >> 6;
    const int sl2 = (tid + 256) >> 6;
    const int sl3 = (tid + 512) >> 6;
    const int cc  = tid & 63;
    const int wg1 = w0 - 1 + sl1, wg2 = w0 - 1 + sl2, wg3 = w0 - 1 + sl3;
    const bool v1 = (wg1 >= 0) && (wg1 < WD);
    const bool v2 = (wg2 >= 0) && (wg2 < WD);
    const bool v3 = (tid < 128) && (wg3 < WD);
    const float4* s1 = (const float4*)x + ((b * HD) * WD + wg1) * C4D + cc;
    const float4* s2 = (const float4*)x + ((b * HD) * WD + wg2) * C4D + cc;
    const float4* s3 = (const float4*)x + ((b * HD) * WD + wg3) * C4D + cc;

    // ---- compute-role: uniform taps (center (1,1) excluded)
    const float4* kp = (const float4*)ker;
    const float4 k00 = kp[0 * C4D + c4];
    const float4 k01 = kp[1 * C4D + c4];
    const float4 k02 = kp[2 * C4D + c4];
    const float4 k10 = kp[3 * C4D + c4];
    const float4 k12 = kp[5 * C4D + c4];
    const float4 k20 = kp[6 * C4D + c4];
    const float4 k21 = kp[7 * C4D + c4];
    const float4 k22 = kp[8 * C4D + c4];

    const int jw     = 2 * wslot;
    const int sbase  = jw * C4D + c4;
    const int out_b0 = ((b * HD) * WD + (w0 + jw)) * C4D + c4;
    float4* op = (float4*)out;

    // Prologue: pairs 0,1 (rows h0-1..h0+2) into stages 0,1.
    COPY_PAIR(stg,                 h0 - 1);
    CP_COMMIT();
    COPY_PAIR(stg + 2 * SLICE_F4,  h0 + 1);
    CP_COMMIT();

    float4 a00 = zf, a10 = zf;   // partials for w = w0+jw
    float4 a01 = zf, a11 = zf;   // partials for w = w0+jw+1

    // 8 pairs cover input rows h0-1 .. h0+14.
    #pragma unroll
    for (int p = 0; p < 8; ++p) {
        CP_WAIT1();              // pair p landed (in-order groups)
        __syncthreads();         // consume(p-1) complete on all threads

        // Prefetch pair p+2 into stage (p+2)%3 (WAR-safe: stage last read
        // at pair p-1, ordered before this barrier).
        if (p < 6) {
            float4* dst = stg + ((p + 2) % NSP) * 2 * SLICE_F4;
            COPY_PAIR(dst, h0 - 1 + 2 * (p + 2));
        }
        CP_COMMIT();

        float4* stagebase = stg + (p % NSP) * 2 * SLICE_F4;
        CONSUME(2 * p,     0, stagebase);
        CONSUME(2 * p + 1, 1, stagebase);
    }
}

extern "C" void kernel_launch(void* const* d_in, const int* in_sizes, int n_in,
                              void* d_out, int out_size) {
    const float* x   = (const float*)d_in[0];   // [32,56,56,256]
    const float* ker = (const float*)d_in[1];   // [3,3,256]
    float*       outp = (float*)d_out;

    cudaFuncSetAttribute(contour_integration_kernel,
                         cudaFuncAttributeMaxDynamicSharedMemorySize, SMEM_BYTES);

    dim3 block(C4D, WSLOT);                         // 64 x 4 = 256 threads
    dim3 grid(WD / W_BLK, HD / H_SEG, BD);          // 7 x 4 x 32 = 896 blocks
    contour_integration_kernel<<<grid, block, SMEM_BYTES>>>(x, ker, outp);
}

// round 14
// speedup vs baseline: 1.0616x; 1.0616x over previous
#include <cuda_runtime.h>
#include <cuda_bf16.h>

// ContourIntegrationLayer: depthwise 3x3 conv (center tap zeroed) + residual.
// x: [B=32, H=56, W=56, C=256] fp32 NHWC ; kernel: [3,3,256] fp32.
//
// R13: R11 (cp.async ring, w-pair per thread, zero-slice boundary, one
// wait+barrier per row) with lookahead deepened 2 -> 3 rows: NS=5 stages
// (50KB dynamic smem), prefetch row i+3, wait_group 3. Ring indices are
// compile-time constants under the fully unrolled loop. Consume path is
// identical to R11 (the R12 regression showed issue bloat must be avoided).

#define BD 32
#define HD 56
#define WD 56
#define C4D 64                 // 256/4 float4 lanes
#define H_SEG 14
#define W_BLK 8                // w per block
#define WSLOT 4
#define NS 5                   // ring stages
#define NSLICE (W_BLK + 2)     // 10 slices per stage
#define SLICE_F4 (NSLICE * C4D)    // 640 float4 = 10KB
#define ROWSTRIDE (WD * C4D)       // 3584 float4 per image row
#define SMEM_BYTES (NS * SLICE_F4 * 16)   // 51200

__device__ __forceinline__ void cp16(float4* dst_smem, const float4* src) {
    unsigned d = (unsigned)__cvta_generic_to_shared(dst_smem);
    asm volatile("cp.async.cg.shared.global [%0], [%1], 16;" :: "r"(d), "l"(src));
}
#define CP_COMMIT() asm volatile("cp.async.commit_group;")
#define CP_WAIT3()  asm volatile("cp.async.wait_group 3;")

__device__ __forceinline__ void fma4(float4& a, const float4& k, const float4& v) {
    a.x = fmaf(k.x, v.x, a.x);
    a.y = fmaf(k.y, v.y, a.y);
    a.z = fmaf(k.z, v.z, a.z);
    a.w = fmaf(k.w, v.w, a.w);
}
__device__ __forceinline__ void add4(float4& a, const float4& v) {
    a.x += v.x; a.y += v.y; a.z += v.z; a.w += v.w;
}

__global__ __launch_bounds__(256, 3)
void contour_integration_kernel(const float* __restrict__ x,
                                const float* __restrict__ ker,
                                float* __restrict__ out) {
    extern __shared__ __align__(16) float4 stg[];   // [NS][SLICE_F4]

    const int c4    = threadIdx.x;              // 0..63
    const int wslot = threadIdx.y;              // 0..3
    const int tid   = c4 + wslot * C4D;         // 0..255
    const int w0    = blockIdx.x * W_BLK;
    const int h0    = blockIdx.y * H_SEG;
    const int b     = blockIdx.z;

    const float4 zf = make_float4(0.f, 0.f, 0.f, 0.f);

    // Permanent zero slices for w outside the image (cp never writes them).
    if (w0 == 0 && tid < C4D) {
        #pragma unroll
        for (int s = 0; s < NS; ++s) stg[s * SLICE_F4 + tid] = zf;
    }
    if (w0 + W_BLK == WD && tid < C4D) {
        #pragma unroll
        for (int s = 0; s < NS; ++s)
            stg[s * SLICE_F4 + (NSLICE - 1) * C4D + tid] = zf;
    }

    // ---- copy-role: 640 chunks/stage; thread does tid, tid+256, (+512 if tid<128)
    const int sl1 = tid >> 6;
    const int sl2 = (tid + 256) >> 6;
    const int sl3 = (tid + 512) >> 6;
    const int cc  = tid & 63;
    const int wg1 = w0 - 1 + sl1, wg2 = w0 - 1 + sl2, wg3 = w0 - 1 + sl3;
    const bool v1 = (wg1 >= 0) && (wg1 < WD);
    const bool v2 = (wg2 >= 0) && (wg2 < WD);
    const bool v3 = (tid < 128) && (wg3 < WD);
    const float4* s1 = (const float4*)x + ((b * HD) * WD + wg1) * C4D + cc;
    const float4* s2 = (const float4*)x + ((b * HD) * WD + wg2) * C4D + cc;
    const float4* s3 = (const float4*)x + ((b * HD) * WD + wg3) * C4D + cc;

    // ---- compute-role: uniform taps (center (1,1) excluded)
    const float4* kp = (const float4*)ker;
    const float4 k00 = kp[0 * C4D + c4];
    const float4 k01 = kp[1 * C4D + c4];
    const float4 k02 = kp[2 * C4D + c4];
    const float4 k10 = kp[3 * C4D + c4];
    const float4 k12 = kp[5 * C4D + c4];
    const float4 k20 = kp[6 * C4D + c4];
    const float4 k21 = kp[7 * C4D + c4];
    const float4 k22 = kp[8 * C4D + c4];

    const int jw     = 2 * wslot;
    const int sbase  = jw * C4D + c4;
    const int out_b0 = ((b * HD) * WD + (w0 + jw)) * C4D + c4;
    float4* op = (float4*)out;

    // Prologue: rows h0-1, h0, h0+1 into stages 0,1,2 (three commit groups).
    #pragma unroll
    for (int i = 0; i < 3; ++i) {
        const int r = h0 - 1 + i;
        if (r >= 0) {                          // r < HD always here
            const int ro = r * ROWSTRIDE;
            float4* dst = stg + i * SLICE_F4;
            if (v1) cp16(dst + tid,       s1 + ro);
            if (v2) cp16(dst + tid + 256, s2 + ro);
            if (v3) cp16(dst + tid + 512, s3 + ro);
        }
        CP_COMMIT();
    }

    float4 a00 = zf, a10 = zf;   // partials for w = w0+jw
    float4 a01 = zf, a11 = zf;   // partials for w = w0+jw+1

    // Consume input rows r = h0-1+i, i = 0..H_SEG+1 (16 rows).
    #pragma unroll
    for (int i = 0; i <= H_SEG + 1; ++i) {
        // Prefetch row i+3 into stage (i+3)%NS (last read at iter i-2,
        // ordered before barrier i-1 -> WAR-safe).
        if (i + 3 <= H_SEG + 1) {
            const int rn = h0 + 2 + i;
            if (rn < HD) {
                float4* dst = stg + ((i + 3) % NS) * SLICE_F4;
                const int ro = rn * ROWSTRIDE;
                if (v1) cp16(dst + tid,       s1 + ro);
                if (v2) cp16(dst + tid + 256, s2 + ro);
                if (v3) cp16(dst + tid + 512, s3 + ro);
            }
        }
        CP_COMMIT();
        CP_WAIT3();                           // groups <= i complete
        __syncthreads();

        const int r = h0 - 1 + i;
        float4 xs0, xs1, xs2, xs3;
        if (r >= 0 && r < HD) {
            const float4* sp = stg + (i % NS) * SLICE_F4 + sbase;
            xs0 = sp[0]; xs1 = sp[C4D]; xs2 = sp[2 * C4D]; xs3 = sp[3 * C4D];
        } else {
            xs0 = zf; xs1 = zf; xs2 = zf; xs3 = zf;
        }

        // bottom taps of row r close out[r-1] for both w.
        if (i >= 2) {
            float4 o0 = a00;
            fma4(o0, k20, xs0); fma4(o0, k21, xs1); fma4(o0, k22, xs2);
            float4 o1 = a01;
            fma4(o1, k20, xs1); fma4(o1, k21, xs2); fma4(o1, k22, xs3);
            const int ob = out_b0 + (r - 1) * ROWSTRIDE;
            __stcs(op + ob, o0);
            __stcs(op + ob + C4D, o1);
        }

        // advance partials: mid taps + residual -> out[r]; top taps -> out[r+1]
        float4 A0 = a10;
        add4(A0, xs1);
        fma4(A0, k10, xs0); fma4(A0, k12, xs2);
        float4 B0 = zf;
        fma4(B0, k00, xs0); fma4(B0, k01, xs1); fma4(B0, k02, xs2);
        a00 = A0; a10 = B0;

        float4 A1 = a11;
        add4(A1, xs2);
        fma4(A1, k10, xs1); fma4(A1, k12, xs3);
        float4 B1 = zf;
        fma4(B1, k00, xs1); fma4(B1, k01, xs2); fma4(B1, k02, xs3);
        a01 = A1; a11 = B1;
    }
}

extern "C" void kernel_launch(void* const* d_in, const int* in_sizes, int n_in,
                              void* d_out, int out_size) {
    const float* x   = (const float*)d_in[0];   // [32,56,56,256]
    const float* ker = (const float*)d_in[1];   // [3,3,256]
    float*       outp = (float*)d_out;

    cudaFuncSetAttribute(contour_integration_kernel,
                         cudaFuncAttributeMaxDynamicSharedMemorySize, SMEM_BYTES);

    dim3 block(C4D, WSLOT);                     // 64 x 4 = 256 threads
    dim3 grid(WD / W_BLK, HD / H_SEG, BD);      // 7 x 4 x 32 = 896 blocks
    contour_integration_kernel<<<grid, block, SMEM_BYTES>>>(x, ker, outp);
}